// round 5
// baseline (speedup 1.0000x reference)
#include <cuda_runtime.h>
#include <math.h>

#define SIMS  2048
#define NBITS 256
#define MID   512
#define LN_EPS 1e-5f
#define NCTA  128
#define NTHR  256
#define RPC   16          // rows per CTA in full mode (2048/128)

// ---------------- device scratch (static, no allocation) ----------------
__device__ float    g_probs_cm[NBITS * SIMS];   // [c][s] column-major probs (full mode)
__device__ float    g_w1t[MID * NBITS];         // [m][k]
__device__ float    g_w2t[NBITS * MID];         // [c][m]
__device__ int      g_winner[NBITS * NBITS];    // [t][c] = max j with ids[j,t]==c, else -1
__device__ int      g_Tstar;
__device__ float    g_ps[SIMS];                 // full-mode gathered probs per row
__device__ float    g_pvec[NBITS];              // collapsed row-uniform state
__device__ float    g_h[MID];                   // collapsed hidden
__device__ float    g_part[NCTA * 2];           // collapsed LN partial (sum, sumsq) per CTA
__device__ unsigned g_bar_count;
__device__ unsigned g_bar_gen;

__device__ __forceinline__ float gelu_exact(float x) {
    return 0.5f * x * (1.0f + erff(x * 0.70710678118654752440f));
}
__device__ __forceinline__ float sigmoidf_(float x) {
    return 1.0f / (1.0f + expf(-x));
}

// Writer-side: __syncthreads (CTA happens-before into tid 0) + gpu-scope fence
// (cumulative) + release store; reader: spin + acquire fence. Same protocol as
// cooperative_groups grid.sync.
__device__ __forceinline__ void grid_barrier(unsigned target) {
    __syncthreads();
    if (threadIdx.x == 0) {
        __threadfence();
        unsigned a = atomicAdd(&g_bar_count, 1u);
        if (a == (unsigned)(NCTA - 1)) {
            atomicExch(&g_bar_count, 0u);
            __threadfence();
            atomicExch(&g_bar_gen, target);
        } else {
            while (*((volatile unsigned*)&g_bar_gen) < target) { }
            __threadfence();
        }
    }
    __syncthreads();
}

// ---------------- setup kernels ----------------
__global__ void k_transpose(const float* __restrict__ w1, const float* __restrict__ w2) {
    int b = blockIdx.x, tid = threadIdx.x;
    // w1t[m][k] = w1[k][m]; m = b (0..511)
    g_w1t[b * NBITS + tid] = w1[tid * MID + b];
    if (b < NBITS) {
        // w2t[c][m] = w2[m][c]; c = b
        g_w2t[b * MID + tid]       = w2[tid * NBITS + b];
        g_w2t[b * MID + 256 + tid] = w2[(tid + 256) * NBITS + b];
    }
}

__global__ void k_winners(const int* __restrict__ ids) {
    __shared__ int win[NBITS];
    int t = blockIdx.x, tid = threadIdx.x;
    win[tid] = -1;
    __syncthreads();
    for (int j = tid; j < SIMS; j += NTHR) {
        int c = ids[j * NBITS + t];
        atomicMax(&win[c], j);
    }
    __syncthreads();
    g_winner[t * NBITS + tid] = win[tid];
}

__global__ void k_prep() {
    int tid = threadIdx.x;
    int colhit = 0;
    int found = 1 << 20;
    for (int t = 0; t < NBITS; ++t) {
        if (g_winner[t * NBITS + tid] >= 0) colhit = 1;
        int cnt = __syncthreads_count(colhit);
        if (cnt == NBITS && (t + 1) < found) found = t + 1;
    }
    if (tid == 0) {
        g_Tstar = found;          // > 255 means "never all-hit" -> full mode throughout
        g_bar_count = 0u;         // reset barrier for this replay (stream-ordered before k_main)
        g_bar_gen   = 0u;
    }
}

// ---------------- main persistent kernel ----------------
__global__ void __launch_bounds__(NTHR, 1) k_main(
    const float* __restrict__ xs, const int* __restrict__ ids,
    const float* __restrict__ w1, const float* __restrict__ b1,
    const float* __restrict__ gamma, const float* __restrict__ beta,
    const float* __restrict__ b2, float* __restrict__ out)
{
    __shared__ float As[NBITS * RPC];   // [k][r] 16 KB
    __shared__ float red [RPC * 8];
    __shared__ float red2[RPC * 8];
    __shared__ float s_mu[RPC], s_rs[RPC];
    __shared__ int   s_cid[RPC];
    __shared__ float p_s[NBITS];
    __shared__ float s_pa[8], s_pb[8];

    const int b = blockIdx.x, tid = threadIdx.x;
    const int lane = tid & 31, wrp = tid >> 5;
    const int Tstar = g_Tstar;
    unsigned gen = 0;

    // init: transpose xs -> probs_cm (this CTA owns columns 2b, 2b+1)
    for (int cc = 0; cc < 2; ++cc) {
        int c = 2 * b + cc;
        for (int s = tid; s < SIMS; s += NTHR)
            g_probs_cm[c * SIMS + s] = xs[s * NBITS + c];
    }
    grid_barrier(++gen);

    for (int t = 0; t < NBITS; ++t) {
        if (t < Tstar) {
            // ================= FULL STEP (rows differ) =================
            const int s0 = b * RPC;
            for (int it = 0; it < 16; ++it) {
                int idx = it * NTHR + tid;
                int k = idx >> 4, r = idx & 15;
                As[k * 16 + r] = g_probs_cm[k * SIMS + s0 + r];
            }
            if (tid < RPC) s_cid[tid] = ids[(s0 + tid) * NBITS + t];
            __syncthreads();

            const int m0 = tid, m1 = tid + 256;
            float acc0[RPC], acc1[RPC];
            #pragma unroll
            for (int r = 0; r < RPC; ++r) { acc0[r] = 0.f; acc1[r] = 0.f; }
            const float4* As4 = reinterpret_cast<const float4*>(As);
            #pragma unroll 4
            for (int k = 0; k < NBITS; ++k) {
                float wa = w1[k * MID + m0];
                float wb = w1[k * MID + m1];
                #pragma unroll
                for (int q = 0; q < 4; ++q) {
                    float4 a = As4[k * 4 + q];
                    acc0[4*q+0] = fmaf(a.x, wa, acc0[4*q+0]);
                    acc0[4*q+1] = fmaf(a.y, wa, acc0[4*q+1]);
                    acc0[4*q+2] = fmaf(a.z, wa, acc0[4*q+2]);
                    acc0[4*q+3] = fmaf(a.w, wa, acc0[4*q+3]);
                    acc1[4*q+0] = fmaf(a.x, wb, acc1[4*q+0]);
                    acc1[4*q+1] = fmaf(a.y, wb, acc1[4*q+1]);
                    acc1[4*q+2] = fmaf(a.z, wb, acc1[4*q+2]);
                    acc1[4*q+3] = fmaf(a.w, wb, acc1[4*q+3]);
                }
            }
            const float bb0 = b1[m0], bb1 = b1[m1];
            #pragma unroll
            for (int r = 0; r < RPC; ++r) {
                acc0[r] = gelu_exact(acc0[r] + bb0);
                acc1[r] = gelu_exact(acc1[r] + bb1);
            }
            // LN stats per row
            #pragma unroll
            for (int r = 0; r < RPC; ++r) {
                float s1v = acc0[r] + acc1[r];
                float s2v = acc0[r]*acc0[r] + acc1[r]*acc1[r];
                #pragma unroll
                for (int o = 16; o; o >>= 1) {
                    s1v += __shfl_down_sync(0xffffffffu, s1v, o);
                    s2v += __shfl_down_sync(0xffffffffu, s2v, o);
                }
                if (lane == 0) { red[r*8 + wrp] = s1v; red2[r*8 + wrp] = s2v; }
            }
            __syncthreads();
            if (tid < RPC) {
                float s1v = 0.f, s2v = 0.f;
                #pragma unroll
                for (int i = 0; i < 8; ++i) { s1v += red[tid*8 + i]; s2v += red2[tid*8 + i]; }
                float mu  = s1v * (1.0f / MID);
                float var = s2v * (1.0f / MID) - mu * mu;
                s_mu[tid] = mu;
                s_rs[tid] = rsqrtf(var + LN_EPS);
            }
            __syncthreads();
            const float ga0 = gamma[m0], ga1 = gamma[m1];
            const float be0 = beta[m0],  be1 = beta[m1];
            #pragma unroll
            for (int r = 0; r < RPC; ++r) {
                float mu = s_mu[r], rs = s_rs[r];
                float hn0 = (acc0[r] - mu) * rs * ga0 + be0;
                float hn1 = (acc1[r] - mu) * rs * ga1 + be1;
                int c = s_cid[r];
                float pv = hn0 * g_w2t[c * MID + m0] + hn1 * g_w2t[c * MID + m1];
                #pragma unroll
                for (int o = 16; o; o >>= 1) pv += __shfl_down_sync(0xffffffffu, pv, o);
                if (lane == 0) red[r*8 + wrp] = pv;
            }
            __syncthreads();
            if (tid < RPC) {
                float pv = 0.f;
                #pragma unroll
                for (int i = 0; i < 8; ++i) pv += red[tid*8 + i];
                int c = s_cid[tid];
                g_ps[s0 + tid] = sigmoidf_(pv + b2[c]);
            }
            grid_barrier(++gen);
            // scatter columns 2b, 2b+1 (winner = max j, XLA last-update-wins)
            for (int cc = 0; cc < 2; ++cc) {
                int c = 2 * b + cc;
                int wj = g_winner[t * NBITS + c];
                if (wj >= 0) {
                    float v = g_ps[wj];
                    for (int s = tid; s < SIMS; s += NTHR) g_probs_cm[c * SIMS + s] = v;
                    if (tid == 0) g_pvec[c] = v;
                }
            }
            grid_barrier(++gen);
        } else {
            // ================= COLLAPSED STEP (rows identical) =================
            // stage 1: h[m] for m in [4b, 4b+4), LN partials
            for (int i = tid; i < NBITS; i += NTHR) p_s[i] = g_pvec[i];
            __syncthreads();
            {
                int mloc = tid >> 6;          // 0..3
                int g    = tid & 63;
                int m    = 4 * b + mloc;
                float acc = 0.f;
                #pragma unroll
                for (int j = 0; j < 4; ++j) {
                    int k = g + 64 * j;
                    acc = fmaf(p_s[k], g_w1t[m * NBITS + k], acc);
                }
                #pragma unroll
                for (int o = 16; o; o >>= 1) acc += __shfl_down_sync(0xffffffffu, acc, o);
                if (lane == 0) s_pa[wrp] = acc;
            }
            __syncthreads();
            if (tid < 4) {
                float hv = s_pa[2*tid] + s_pa[2*tid + 1] + b1[4*b + tid];
                hv = gelu_exact(hv);
                g_h[4*b + tid] = hv;
                s_pb[tid]     = hv;
                s_pb[4 + tid] = hv * hv;
            }
            __syncthreads();
            if (tid == 0) {
                g_part[2*b]     = s_pb[0] + s_pb[1] + s_pb[2] + s_pb[3];
                g_part[2*b + 1] = s_pb[4] + s_pb[5] + s_pb[6] + s_pb[7];
            }
            grid_barrier(++gen);

            // stage 2: deterministic LN-stat reduction, then out[c] for c in {2b, 2b+1}
            float sv = 0.f, qv = 0.f;
            if (tid < NCTA) { sv = g_part[2*tid]; qv = g_part[2*tid + 1]; }
            #pragma unroll
            for (int o = 16; o; o >>= 1) {
                sv += __shfl_down_sync(0xffffffffu, sv, o);
                qv += __shfl_down_sync(0xffffffffu, qv, o);
            }
            if (lane == 0) { s_pa[wrp] = sv; s_pb[wrp] = qv; }
            __syncthreads();
            float ssum = 0.f, qsum = 0.f;
            #pragma unroll
            for (int i = 0; i < 8; ++i) { ssum += s_pa[i]; qsum += s_pb[i]; }
            float mu  = ssum * (1.0f / MID);
            float var = qsum * (1.0f / MID) - mu * mu;
            float rs  = rsqrtf(var + LN_EPS);

            float h0 = g_h[tid], h1 = g_h[tid + 256];
            float hn0 = (h0 - mu) * rs * gamma[tid]       + beta[tid];
            float hn1 = (h1 - mu) * rs * gamma[tid + 256] + beta[tid + 256];
            int c0 = 2 * b, c1 = 2 * b + 1;
            float a0 = hn0 * g_w2t[c0 * MID + tid] + hn1 * g_w2t[c0 * MID + tid + 256];
            float a1 = hn0 * g_w2t[c1 * MID + tid] + hn1 * g_w2t[c1 * MID + tid + 256];
            #pragma unroll
            for (int o = 16; o; o >>= 1) {
                a0 += __shfl_down_sync(0xffffffffu, a0, o);
                a1 += __shfl_down_sync(0xffffffffu, a1, o);
            }
            __syncthreads();                 // protect s_pa/s_pb reuse
            if (lane == 0) { s_pa[wrp] = a0; s_pb[wrp] = a1; }
            __syncthreads();
            if (tid < 2) {
                int c = 2 * b + tid;
                const float* buf = tid ? s_pb : s_pa;
                float tot = 0.f;
                #pragma unroll
                for (int i = 0; i < 8; ++i) tot += buf[i];
                if (g_winner[t * NBITS + c] >= 0)
                    g_pvec[c] = sigmoidf_(tot + b2[c]);
            }
            grid_barrier(++gen);
        }
    }

    // write output [2048][256] row-major
    {
        const int s0 = b * RPC;
        if (Tstar <= NBITS - 1) {
            float pv = g_pvec[tid];
            #pragma unroll
            for (int r = 0; r < RPC; ++r)
                out[(s0 + r) * NBITS + tid] = pv;
        } else {
            #pragma unroll
            for (int r = 0; r < RPC; ++r)
                out[(s0 + r) * NBITS + tid] = g_probs_cm[tid * SIMS + s0 + r];
        }
    }
}

// ---------------- launch ----------------
extern "C" void kernel_launch(void* const* d_in, const int* in_sizes, int n_in,
                              void* d_out, int out_size) {
    (void)in_sizes; (void)n_in; (void)out_size;
    const float* xs    = (const float*)d_in[0];
    const int*   ids   = (const int*)  d_in[1];
    const float* w1    = (const float*)d_in[2];
    const float* b1    = (const float*)d_in[3];
    const float* gamma = (const float*)d_in[4];
    const float* beta  = (const float*)d_in[5];
    const float* w2    = (const float*)d_in[6];
    const float* b2    = (const float*)d_in[7];
    float* out = (float*)d_out;

    k_transpose<<<MID, NTHR>>>(w1, w2);
    k_winners<<<NBITS, NTHR>>>(ids);
    k_prep<<<1, NBITS>>>();
    k_main<<<NCTA, NTHR>>>(xs, ids, w1, b1, gamma, beta, b2, out);
}

// round 9
// speedup vs baseline: 1.4209x; 1.4209x over previous
#include <cuda_runtime.h>
#include <math.h>
#include <stdint.h>

#define SIMS  2048
#define NBITS 256
#define MID   512
#define LN_EPS 1e-5f
#define NCTA  128
#define NTHR  256
#define RPC   16          // rows per CTA in full mode (2048/128)
#define CLN   8           // cluster size for collapsed phase
#define CTHR  1024

// ---------------- device scratch (static, no allocation) ----------------
__device__ float    g_probs_cm[NBITS * SIMS];   // [c][s] column-major probs (full mode)
__device__ float    g_w1t[MID * NBITS];         // [m][k]
__device__ float    g_w2t[NBITS * MID];         // [c][m]
__device__ int      g_winner[NBITS * NBITS];    // [t][c] = max j with ids[j,t]==c, else -1
__device__ int      g_Tstar;
__device__ float    g_ps[SIMS];                 // full-mode gathered probs per row
__device__ float    g_pvec[NBITS];              // row-uniform state handoff
__device__ unsigned g_bar_count;
__device__ unsigned g_bar_gen;

__device__ __forceinline__ float gelu_exact(float x) {
    return 0.5f * x * (1.0f + erff(x * 0.70710678118654752440f));
}
__device__ __forceinline__ float sigmoidf_(float x) {
    return 1.0f / (1.0f + expf(-x));
}

__device__ __forceinline__ void grid_barrier(unsigned target) {
    __syncthreads();
    if (threadIdx.x == 0) {
        __threadfence();
        unsigned a = atomicAdd(&g_bar_count, 1u);
        if (a == (unsigned)(NCTA - 1)) {
            atomicExch(&g_bar_count, 0u);
            __threadfence();
            atomicExch(&g_bar_gen, target);
        } else {
            while (*((volatile unsigned*)&g_bar_gen) < target) { }
            __threadfence();
        }
    }
    __syncthreads();
}

// ---- cluster helpers (DSMEM + cluster barrier) ----
__device__ __forceinline__ uint32_t smem_u32(const void* p) {
    uint32_t a;
    asm("{ .reg .u64 t; cvta.to.shared.u64 t, %1; cvt.u32.u64 %0, t; }" : "=r"(a) : "l"(p));
    return a;
}
__device__ __forceinline__ void dsmem_st_f32(uint32_t laddr, uint32_t rank, float v) {
    uint32_t ra;
    asm volatile("mapa.shared::cluster.u32 %0, %1, %2;" : "=r"(ra) : "r"(laddr), "r"(rank));
    asm volatile("st.shared::cluster.f32 [%0], %1;" :: "r"(ra), "f"(v) : "memory");
}
__device__ __forceinline__ void cluster_bar() {
    asm volatile("barrier.cluster.arrive.aligned;" ::: "memory");
    asm volatile("barrier.cluster.wait.aligned;" ::: "memory");
}
__device__ __forceinline__ uint32_t ctarank_() {
    uint32_t r; asm("mov.u32 %0, %%cluster_ctarank;" : "=r"(r)); return r;
}

// ---------------- setup kernels ----------------
__global__ void k_transpose(const float* __restrict__ w1, const float* __restrict__ w2) {
    int b = blockIdx.x, tid = threadIdx.x;
    g_w1t[b * NBITS + tid] = w1[tid * MID + b];
    if (b < NBITS) {
        g_w2t[b * MID + tid]       = w2[tid * NBITS + b];
        g_w2t[b * MID + 256 + tid] = w2[(tid + 256) * NBITS + b];
    }
}

__global__ void k_winners(const int* __restrict__ ids) {
    __shared__ int win[NBITS];
    int t = blockIdx.x, tid = threadIdx.x;
    win[tid] = -1;
    __syncthreads();
    for (int j = tid; j < SIMS; j += NTHR) {
        int c = ids[j * NBITS + t];
        atomicMax(&win[c], j);
    }
    __syncthreads();
    g_winner[t * NBITS + tid] = win[tid];
}

__global__ void k_prep() {
    int tid = threadIdx.x;
    int colhit = 0;
    int found = 1 << 20;
    for (int t = 0; t < NBITS; ++t) {
        if (g_winner[t * NBITS + tid] >= 0) colhit = 1;
        int cnt = __syncthreads_count(colhit);
        if (cnt == NBITS && (t + 1) < found) found = t + 1;
    }
    if (tid == 0) {
        g_Tstar = found;
        g_bar_count = 0u;
        g_bar_gen   = 0u;
    }
}

// ---------------- full-phase kernel (steps t < Tstar) ----------------
__global__ void __launch_bounds__(NTHR, 1) k_full(
    const float* __restrict__ xs, const int* __restrict__ ids,
    const float* __restrict__ w1, const float* __restrict__ b1,
    const float* __restrict__ gamma, const float* __restrict__ beta,
    const float* __restrict__ b2, float* __restrict__ out)
{
    __shared__ float As[NBITS * RPC];
    __shared__ float red [RPC * 8];
    __shared__ float red2[RPC * 8];
    __shared__ float s_mu[RPC], s_rs[RPC];
    __shared__ int   s_cid[RPC];

    const int b = blockIdx.x, tid = threadIdx.x;
    const int lane = tid & 31, wrp = tid >> 5;
    const int Tstar = g_Tstar;
    unsigned gen = 0;

    // init: transpose xs -> probs_cm (this CTA owns columns 2b, 2b+1)
    for (int cc = 0; cc < 2; ++cc) {
        int c = 2 * b + cc;
        for (int s = tid; s < SIMS; s += NTHR)
            g_probs_cm[c * SIMS + s] = xs[s * NBITS + c];
    }
    grid_barrier(++gen);

    const int nfull = (Tstar < NBITS) ? Tstar : NBITS;
    for (int t = 0; t < nfull; ++t) {
        const int s0 = b * RPC;
        for (int it = 0; it < 16; ++it) {
            int idx = it * NTHR + tid;
            int k = idx >> 4, r = idx & 15;
            As[k * 16 + r] = g_probs_cm[k * SIMS + s0 + r];
        }
        if (tid < RPC) s_cid[tid] = ids[(s0 + tid) * NBITS + t];
        __syncthreads();

        const int m0 = tid, m1 = tid + 256;
        float acc0[RPC], acc1[RPC];
        #pragma unroll
        for (int r = 0; r < RPC; ++r) { acc0[r] = 0.f; acc1[r] = 0.f; }
        const float4* As4 = reinterpret_cast<const float4*>(As);
        #pragma unroll 4
        for (int k = 0; k < NBITS; ++k) {
            float wa = w1[k * MID + m0];
            float wb = w1[k * MID + m1];
            #pragma unroll
            for (int q = 0; q < 4; ++q) {
                float4 a = As4[k * 4 + q];
                acc0[4*q+0] = fmaf(a.x, wa, acc0[4*q+0]);
                acc0[4*q+1] = fmaf(a.y, wa, acc0[4*q+1]);
                acc0[4*q+2] = fmaf(a.z, wa, acc0[4*q+2]);
                acc0[4*q+3] = fmaf(a.w, wa, acc0[4*q+3]);
                acc1[4*q+0] = fmaf(a.x, wb, acc1[4*q+0]);
                acc1[4*q+1] = fmaf(a.y, wb, acc1[4*q+1]);
                acc1[4*q+2] = fmaf(a.z, wb, acc1[4*q+2]);
                acc1[4*q+3] = fmaf(a.w, wb, acc1[4*q+3]);
            }
        }
        const float bb0 = b1[m0], bb1 = b1[m1];
        #pragma unroll
        for (int r = 0; r < RPC; ++r) {
            acc0[r] = gelu_exact(acc0[r] + bb0);
            acc1[r] = gelu_exact(acc1[r] + bb1);
        }
        #pragma unroll
        for (int r = 0; r < RPC; ++r) {
            float s1v = acc0[r] + acc1[r];
            float s2v = acc0[r]*acc0[r] + acc1[r]*acc1[r];
            #pragma unroll
            for (int o = 16; o; o >>= 1) {
                s1v += __shfl_down_sync(0xffffffffu, s1v, o);
                s2v += __shfl_down_sync(0xffffffffu, s2v, o);
            }
            if (lane == 0) { red[r*8 + wrp] = s1v; red2[r*8 + wrp] = s2v; }
        }
        __syncthreads();
        if (tid < RPC) {
            float s1v = 0.f, s2v = 0.f;
            #pragma unroll
            for (int i = 0; i < 8; ++i) { s1v += red[tid*8 + i]; s2v += red2[tid*8 + i]; }
            float mu  = s1v * (1.0f / MID);
            float var = s2v * (1.0f / MID) - mu * mu;
            s_mu[tid] = mu;
            s_rs[tid] = rsqrtf(var + LN_EPS);
        }
        __syncthreads();
        const float ga0 = gamma[m0], ga1 = gamma[m1];
        const float be0 = beta[m0],  be1 = beta[m1];
        #pragma unroll
        for (int r = 0; r < RPC; ++r) {
            float mu = s_mu[r], rs = s_rs[r];
            float hn0 = (acc0[r] - mu) * rs * ga0 + be0;
            float hn1 = (acc1[r] - mu) * rs * ga1 + be1;
            int c = s_cid[r];
            float pv = hn0 * g_w2t[c * MID + m0] + hn1 * g_w2t[c * MID + m1];
            #pragma unroll
            for (int o = 16; o; o >>= 1) pv += __shfl_down_sync(0xffffffffu, pv, o);
            if (lane == 0) red[r*8 + wrp] = pv;
        }
        __syncthreads();
        if (tid < RPC) {
            float pv = 0.f;
            #pragma unroll
            for (int i = 0; i < 8; ++i) pv += red[tid*8 + i];
            int c = s_cid[tid];
            g_ps[s0 + tid] = sigmoidf_(pv + b2[c]);
        }
        grid_barrier(++gen);
        for (int cc = 0; cc < 2; ++cc) {
            int c = 2 * b + cc;
            int wj = g_winner[t * NBITS + c];
            if (wj >= 0) {
                float v = g_ps[wj];
                for (int s = tid; s < SIMS; s += NTHR) g_probs_cm[c * SIMS + s] = v;
                if (tid == 0) g_pvec[c] = v;
            }
        }
        grid_barrier(++gen);
    }

    // fallback output only if the collapse never engages
    if (Tstar > NBITS - 1) {
        const int s0 = b * RPC;
        #pragma unroll
        for (int r = 0; r < RPC; ++r)
            out[(s0 + r) * NBITS + tid] = g_probs_cm[tid * SIMS + s0 + r];
    }
}

// ---------------- collapsed-phase kernel: one 8-CTA cluster ----------------
struct CollSmem {
    float w1s[64 * NBITS];      // rows [64r, 64r+64) of w1t        64 KB
    float w2s[32 * MID];        // cols [32r, 32r+32) of w2t        64 KB
    int   winner_s[NBITS * 32]; // [t][cloc] for this CTA's cols    32 KB
    float h_s[MID];
    float hn_s[MID];
    float p_s[NBITS];
    float gamma_s[MID], beta_s[MID];
    float b1_s[64], b2_s[32];
    float red_s[64];
    float stat_s[2];
};

__global__ void __cluster_dims__(CLN, 1, 1) __launch_bounds__(CTHR, 1)
k_collapsed(const float* __restrict__ b1g, const float* __restrict__ gammag,
            const float* __restrict__ betag, const float* __restrict__ b2g,
            float* __restrict__ out)
{
    extern __shared__ char raw[];
    CollSmem* sm = reinterpret_cast<CollSmem*>(raw);
    const int Tstar = g_Tstar;
    if (Tstar > NBITS - 1) return;          // uniform across cluster

    const int tid = threadIdx.x;
    const int lane = tid & 31, wrp = tid >> 5;
    const uint32_t r = ctarank_();

    // ---- preload (all CTA-local) ----
    {
        float4* d1 = reinterpret_cast<float4*>(sm->w1s);
        const float4* s1 = reinterpret_cast<const float4*>(g_w1t + (64u * r) * NBITS);
        for (int i = tid; i < 64 * NBITS / 4; i += CTHR) d1[i] = s1[i];
        float4* d2 = reinterpret_cast<float4*>(sm->w2s);
        const float4* s2 = reinterpret_cast<const float4*>(g_w2t + (32u * r) * MID);
        for (int i = tid; i < 32 * MID / 4; i += CTHR) d2[i] = s2[i];
        for (int i = tid; i < NBITS * 32; i += CTHR) {
            int t = i >> 5, c = i & 31;
            sm->winner_s[i] = g_winner[t * NBITS + 32 * r + c];
        }
        for (int i = tid; i < MID; i += CTHR) {
            sm->gamma_s[i] = gammag[i];
            sm->beta_s[i]  = betag[i];
        }
        if (tid < 64) sm->b1_s[tid] = b1g[64 * r + tid];
        if (tid < 32) sm->b2_s[tid] = b2g[32 * r + tid];
        for (int i = tid; i < NBITS; i += CTHR) sm->p_s[i] = g_pvec[i];
    }
    __syncthreads();
    cluster_bar();         // peers' smem initialized before any DSMEM traffic

    for (int t = Tstar; t < NBITS; ++t) {
        // ---- GEMV1: this CTA computes h for m in [64r, 64r+64) ----
        {
            int mloc = tid >> 4;
            int g    = tid & 15;
            const float* wrow = &sm->w1s[mloc * NBITS];
            float acc = 0.f;
            #pragma unroll
            for (int j = 0; j < 16; ++j) {
                int k = g + 16 * j;
                acc = fmaf(sm->p_s[k], wrow[k], acc);
            }
            #pragma unroll
            for (int o = 8; o; o >>= 1) acc += __shfl_down_sync(0xffffffffu, acc, o, 16);
            if (g == 0) {
                float hv = gelu_exact(acc + sm->b1_s[mloc]);
                uint32_t la = smem_u32(&sm->h_s[64 * r + mloc]);
                #pragma unroll
                for (uint32_t rk = 0; rk < CLN; ++rk) dsmem_st_f32(la, rk, hv);
            }
        }
        cluster_bar();     // h_s[512] complete in every CTA

        // ---- LN stats (redundant per CTA, fixed order) + hn precompute ----
        {
            float v = 0.f, v2 = 0.f;
            if (tid < MID) { float hv = sm->h_s[tid]; v = hv; v2 = hv * hv; }
            #pragma unroll
            for (int o = 16; o; o >>= 1) {
                v  += __shfl_down_sync(0xffffffffu, v,  o);
                v2 += __shfl_down_sync(0xffffffffu, v2, o);
            }
            if (lane == 0) { sm->red_s[wrp] = v; sm->red_s[32 + wrp] = v2; }
            __syncthreads();
            if (tid == 0) {
                float s = 0.f, q = 0.f;
                #pragma unroll
                for (int i = 0; i < 32; ++i) { s += sm->red_s[i]; q += sm->red_s[32 + i]; }
                float mu  = s * (1.0f / MID);
                float var = q * (1.0f / MID) - mu * mu;
                sm->stat_s[0] = mu;
                sm->stat_s[1] = rsqrtf(var + LN_EPS);
            }
            __syncthreads();
            if (tid < MID) {
                float mu = sm->stat_s[0], rs = sm->stat_s[1];
                sm->hn_s[tid] = (sm->h_s[tid] - mu) * rs * sm->gamma_s[tid] + sm->beta_s[tid];
            }
            __syncthreads();
        }

        // ---- GEMV2: this CTA computes out cols [32r, 32r+32), updates p ----
        {
            int cloc = tid >> 5;
            const float* w2row = &sm->w2s[cloc * MID];
            float acc = 0.f;
            #pragma unroll
            for (int j = 0; j < 16; ++j) {
                int m = lane + 32 * j;
                acc = fmaf(sm->hn_s[m], w2row[m], acc);
            }
            #pragma unroll
            for (int o = 16; o; o >>= 1) acc += __shfl_down_sync(0xffffffffu, acc, o);
            if (lane == 0 && sm->winner_s[t * 32 + cloc] >= 0) {
                float pnew = sigmoidf_(acc + sm->b2_s[cloc]);
                uint32_t la = smem_u32(&sm->p_s[32 * r + cloc]);
                #pragma unroll
                for (uint32_t rk = 0; rk < CLN; ++rk) dsmem_st_f32(la, rk, pnew);
            }
        }
        cluster_bar();     // p_s[256] consistent in every CTA
    }

    // ---- output: rows [256r, 256r+256), all rows = p_s ----
    {
        const float4* p4 = reinterpret_cast<const float4*>(sm->p_s);
        float4* o4 = reinterpret_cast<float4*>(out);
        for (int i = tid; i < 256 * 64; i += CTHR) {
            int srow = 256 * (int)r + (i >> 6);
            int q = i & 63;
            o4[srow * 64 + q] = p4[q];
        }
    }
}

// ---------------- launch ----------------
extern "C" void kernel_launch(void* const* d_in, const int* in_sizes, int n_in,
                              void* d_out, int out_size) {
    (void)in_sizes; (void)n_in; (void)out_size;
    const float* xs    = (const float*)d_in[0];
    const int*   ids   = (const int*)  d_in[1];
    const float* w1    = (const float*)d_in[2];
    const float* b1    = (const float*)d_in[3];
    const float* gamma = (const float*)d_in[4];
    const float* beta  = (const float*)d_in[5];
    const float* w2    = (const float*)d_in[6];
    const float* b2    = (const float*)d_in[7];
    float* out = (float*)d_out;

    cudaFuncSetAttribute(k_collapsed, cudaFuncAttributeMaxDynamicSharedMemorySize,
                         (int)sizeof(CollSmem));

    k_transpose<<<MID, NTHR>>>(w1, w2);
    k_winners<<<NBITS, NTHR>>>(ids);
    k_prep<<<1, NBITS>>>();
    k_full<<<NCTA, NTHR>>>(xs, ids, w1, b1, gamma, beta, b2, out);
    k_collapsed<<<CLN, CTHR, sizeof(CollSmem)>>>(b1, gamma, beta, b2, out);
}

// round 13
// speedup vs baseline: 2.9245x; 2.0582x over previous
#include <cuda_runtime.h>
#include <math.h>
#include <stdint.h>

#define SIMS  2048
#define NBITS 256
#define MID   512
#define LN_EPS 1e-5f
#define NCTA  128
#define NTHR  256
#define RPC   16          // rows per CTA in full mode (2048/128)
#define CLN   8           // cluster size for collapsed phase
#define CTHR_C 512        // threads per CTA in collapsed phase (16 warps)

// ---------------- device scratch (static, no allocation) ----------------
__device__ float    g_probs_cm[NBITS * SIMS];   // [c][s] column-major probs (full mode)
__device__ float    g_w1t[MID * NBITS];         // [m][k]
__device__ float    g_w2t[NBITS * MID];         // [c][m]
__device__ int      g_winner[NBITS * NBITS];    // [t][c] = max j with ids[j,t]==c, else -1
__device__ int      g_Tstar;
__device__ float    g_ps[SIMS];                 // full-mode gathered probs per row
__device__ float    g_pvec[NBITS];              // row-uniform state handoff
__device__ unsigned g_bar_count;
__device__ unsigned g_bar_gen;

__device__ __forceinline__ float gelu_exact(float x) {
    return 0.5f * x * (1.0f + erff(x * 0.70710678118654752440f));
}
__device__ __forceinline__ float sigmoidf_(float x) {
    return 1.0f / (1.0f + expf(-x));
}

__device__ __forceinline__ void grid_barrier(unsigned target) {
    __syncthreads();
    if (threadIdx.x == 0) {
        __threadfence();
        unsigned a = atomicAdd(&g_bar_count, 1u);
        if (a == (unsigned)(NCTA - 1)) {
            atomicExch(&g_bar_count, 0u);
            __threadfence();
            atomicExch(&g_bar_gen, target);
        } else {
            while (*((volatile unsigned*)&g_bar_gen) < target) { }
            __threadfence();
        }
    }
    __syncthreads();
}

// ---- cluster helpers (DSMEM + cluster barrier) ----
__device__ __forceinline__ uint32_t smem_u32(const void* p) {
    uint32_t a;
    asm("{ .reg .u64 t; cvta.to.shared.u64 t, %1; cvt.u32.u64 %0, t; }" : "=r"(a) : "l"(p));
    return a;
}
__device__ __forceinline__ void dsmem_st_f32(uint32_t laddr, uint32_t rank, float v) {
    uint32_t ra;
    asm volatile("mapa.shared::cluster.u32 %0, %1, %2;" : "=r"(ra) : "r"(laddr), "r"(rank));
    asm volatile("st.shared::cluster.f32 [%0], %1;" :: "r"(ra), "f"(v) : "memory");
}
__device__ __forceinline__ void cluster_bar() {
    asm volatile("barrier.cluster.arrive.aligned;" ::: "memory");
    asm volatile("barrier.cluster.wait.aligned;" ::: "memory");
}
__device__ __forceinline__ uint32_t ctarank_() {
    uint32_t r; asm("mov.u32 %0, %%cluster_ctarank;" : "=r"(r)); return r;
}

// ---------------- setup kernels ----------------
// tiled transpose: w1[256][512] -> g_w1t[512][256]
__global__ void k_tr1(const float* __restrict__ w1) {
    __shared__ float tile[32][33];
    const int C = MID, R = NBITS;
    int ct = blockIdx.x * 32, rt = blockIdx.y * 32;
    int tx = threadIdx.x, ty = threadIdx.y;       // 32 x 8
    #pragma unroll
    for (int i = 0; i < 32; i += 8)
        tile[ty + i][tx] = w1[(rt + ty + i) * C + ct + tx];
    __syncthreads();
    #pragma unroll
    for (int i = 0; i < 32; i += 8)
        g_w1t[(ct + ty + i) * R + rt + tx] = tile[tx][ty + i];
}
// tiled transpose: w2[512][256] -> g_w2t[256][512]
__global__ void k_tr2(const float* __restrict__ w2) {
    __shared__ float tile[32][33];
    const int C = NBITS, R = MID;
    int ct = blockIdx.x * 32, rt = blockIdx.y * 32;
    int tx = threadIdx.x, ty = threadIdx.y;
    #pragma unroll
    for (int i = 0; i < 32; i += 8)
        tile[ty + i][tx] = w2[(rt + ty + i) * C + ct + tx];
    __syncthreads();
    #pragma unroll
    for (int i = 0; i < 32; i += 8)
        g_w2t[(ct + ty + i) * R + rt + tx] = tile[tx][ty + i];
}

// winners, coalesced: block b handles t in [32b, 32b+32)
__global__ void k_winners(const int* __restrict__ ids) {
    __shared__ int win[32 * NBITS];               // [tl][c], 32 KB
    int b = blockIdx.x, tid = threadIdx.x;
    for (int i = tid; i < 32 * NBITS; i += NTHR) win[i] = -1;
    __syncthreads();
    for (int idx = tid; idx < SIMS * 32; idx += NTHR) {
        int j = idx >> 5, tl = idx & 31;          // consecutive tid -> consecutive tl: coalesced
        int c = ids[j * NBITS + 32 * b + tl];
        atomicMax(&win[tl * NBITS + c], j);
    }
    __syncthreads();
    for (int i = tid; i < 32 * NBITS; i += NTHR) {
        int tl = i >> 8, c = i & 255;
        g_winner[(32 * b + tl) * NBITS + c] = win[i];
    }
}

// Tstar = max_c (first t with winner[t][c] >= 0) + 1 ; never-hit column -> > 255
__global__ void k_prep() {
    __shared__ int red[NBITS];
    int c = threadIdx.x;
    int first = NBITS;                            // sentinel: never hit
    for (int t = 0; t < NBITS; ++t) {
        if (g_winner[t * NBITS + c] >= 0) { first = t; break; }
    }
    red[c] = first;
    __syncthreads();
    for (int s = 128; s; s >>= 1) {
        if (c < s) red[c] = max(red[c], red[c + s]);
        __syncthreads();
    }
    if (c == 0) {
        g_Tstar = red[0] + 1;
        g_bar_count = 0u;
        g_bar_gen   = 0u;
    }
}

// ---------------- full-phase kernel (steps t < Tstar) ----------------
__global__ void __launch_bounds__(NTHR, 1) k_full(
    const float* __restrict__ xs, const int* __restrict__ ids,
    const float* __restrict__ w1, const float* __restrict__ b1,
    const float* __restrict__ gamma, const float* __restrict__ beta,
    const float* __restrict__ b2, float* __restrict__ out)
{
    __shared__ float As[NBITS * RPC];
    __shared__ float red [RPC * 8];
    __shared__ float red2[RPC * 8];
    __shared__ float s_mu[RPC], s_rs[RPC];
    __shared__ int   s_cid[RPC];

    const int b = blockIdx.x, tid = threadIdx.x;
    const int lane = tid & 31, wrp = tid >> 5;
    const int Tstar = g_Tstar;
    unsigned gen = 0;

    for (int cc = 0; cc < 2; ++cc) {
        int c = 2 * b + cc;
        for (int s = tid; s < SIMS; s += NTHR)
            g_probs_cm[c * SIMS + s] = xs[s * NBITS + c];
    }
    grid_barrier(++gen);

    const int nfull = (Tstar < NBITS) ? Tstar : NBITS;
    for (int t = 0; t < nfull; ++t) {
        const int s0 = b * RPC;
        for (int it = 0; it < 16; ++it) {
            int idx = it * NTHR + tid;
            int k = idx >> 4, r = idx & 15;
            As[k * 16 + r] = g_probs_cm[k * SIMS + s0 + r];
        }
        if (tid < RPC) s_cid[tid] = ids[(s0 + tid) * NBITS + t];
        __syncthreads();

        const int m0 = tid, m1 = tid + 256;
        float acc0[RPC], acc1[RPC];
        #pragma unroll
        for (int r = 0; r < RPC; ++r) { acc0[r] = 0.f; acc1[r] = 0.f; }
        const float4* As4 = reinterpret_cast<const float4*>(As);
        #pragma unroll 4
        for (int k = 0; k < NBITS; ++k) {
            float wa = w1[k * MID + m0];
            float wb = w1[k * MID + m1];
            #pragma unroll
            for (int q = 0; q < 4; ++q) {
                float4 a = As4[k * 4 + q];
                acc0[4*q+0] = fmaf(a.x, wa, acc0[4*q+0]);
                acc0[4*q+1] = fmaf(a.y, wa, acc0[4*q+1]);
                acc0[4*q+2] = fmaf(a.z, wa, acc0[4*q+2]);
                acc0[4*q+3] = fmaf(a.w, wa, acc0[4*q+3]);
                acc1[4*q+0] = fmaf(a.x, wb, acc1[4*q+0]);
                acc1[4*q+1] = fmaf(a.y, wb, acc1[4*q+1]);
                acc1[4*q+2] = fmaf(a.z, wb, acc1[4*q+2]);
                acc1[4*q+3] = fmaf(a.w, wb, acc1[4*q+3]);
            }
        }
        const float bb0 = b1[m0], bb1 = b1[m1];
        #pragma unroll
        for (int r = 0; r < RPC; ++r) {
            acc0[r] = gelu_exact(acc0[r] + bb0);
            acc1[r] = gelu_exact(acc1[r] + bb1);
        }
        #pragma unroll
        for (int r = 0; r < RPC; ++r) {
            float s1v = acc0[r] + acc1[r];
            float s2v = acc0[r]*acc0[r] + acc1[r]*acc1[r];
            #pragma unroll
            for (int o = 16; o; o >>= 1) {
                s1v += __shfl_down_sync(0xffffffffu, s1v, o);
                s2v += __shfl_down_sync(0xffffffffu, s2v, o);
            }
            if (lane == 0) { red[r*8 + wrp] = s1v; red2[r*8 + wrp] = s2v; }
        }
        __syncthreads();
        if (tid < RPC) {
            float s1v = 0.f, s2v = 0.f;
            #pragma unroll
            for (int i = 0; i < 8; ++i) { s1v += red[tid*8 + i]; s2v += red2[tid*8 + i]; }
            float mu  = s1v * (1.0f / MID);
            float var = s2v * (1.0f / MID) - mu * mu;
            s_mu[tid] = mu;
            s_rs[tid] = rsqrtf(var + LN_EPS);
        }
        __syncthreads();
        const float ga0 = gamma[m0], ga1 = gamma[m1];
        const float be0 = beta[m0],  be1 = beta[m1];
        #pragma unroll
        for (int r = 0; r < RPC; ++r) {
            float mu = s_mu[r], rs = s_rs[r];
            float hn0 = (acc0[r] - mu) * rs * ga0 + be0;
            float hn1 = (acc1[r] - mu) * rs * ga1 + be1;
            int c = s_cid[r];
            float pv = hn0 * g_w2t[c * MID + m0] + hn1 * g_w2t[c * MID + m1];
            #pragma unroll
            for (int o = 16; o; o >>= 1) pv += __shfl_down_sync(0xffffffffu, pv, o);
            if (lane == 0) red[r*8 + wrp] = pv;
        }
        __syncthreads();
        if (tid < RPC) {
            float pv = 0.f;
            #pragma unroll
            for (int i = 0; i < 8; ++i) pv += red[tid*8 + i];
            int c = s_cid[tid];
            g_ps[s0 + tid] = sigmoidf_(pv + b2[c]);
        }
        grid_barrier(++gen);
        for (int cc = 0; cc < 2; ++cc) {
            int c = 2 * b + cc;
            int wj = g_winner[t * NBITS + c];
            if (wj >= 0) {
                float v = g_ps[wj];
                for (int s = tid; s < SIMS; s += NTHR) g_probs_cm[c * SIMS + s] = v;
                if (tid == 0) g_pvec[c] = v;
            }
        }
        grid_barrier(++gen);
    }

    if (Tstar > NBITS - 1) {
        const int s0 = b * RPC;
        #pragma unroll
        for (int r = 0; r < RPC; ++r)
            out[(s0 + r) * NBITS + tid] = g_probs_cm[tid * SIMS + s0 + r];
    }
}

// ---------------- collapsed-phase kernel: 8-CTA cluster, weights in registers ----------------
struct CSm {
    alignas(16) float p_s[NBITS];
    float h_s[MID];
    float hn_s[MID];
    float gamma_s[MID], beta_s[MID];
    float b1_s[64], b2_s[32];
    float red_s[32];
    float stat_s[2];
    int   winner_s[NBITS * 32];   // [t][cloc] for this CTA's 32 columns
};

__global__ void __cluster_dims__(CLN, 1, 1) __launch_bounds__(CTHR_C, 1)
k_collapsed(const float* __restrict__ b1g, const float* __restrict__ gammag,
            const float* __restrict__ betag, const float* __restrict__ b2g,
            float* __restrict__ out)
{
    __shared__ CSm sm;            // ~42 KB static
    const int Tstar = g_Tstar;
    if (Tstar > NBITS - 1) return;              // uniform across cluster

    const int tid = threadIdx.x;
    const int lane = tid & 31, wid = tid >> 5;  // 16 warps
    const uint32_t r = ctarank_();

    // ---- smem preload ----
    for (int i = tid; i < NBITS; i += CTHR_C) sm.p_s[i] = g_pvec[i];
    for (int i = tid; i < MID; i += CTHR_C) {
        sm.gamma_s[i] = gammag[i];
        sm.beta_s[i]  = betag[i];
    }
    if (tid < 64) sm.b1_s[tid] = b1g[64 * r + tid];
    if (tid < 32) sm.b2_s[tid] = b2g[32 * r + tid];
    for (int i = tid; i < NBITS * 32; i += CTHR_C) {
        int t = i >> 5, cl = i & 31;
        sm.winner_s[i] = g_winner[t * NBITS + 32 * r + cl];
    }

    // ---- weights into registers (warps 0-7: w1 slice; warps 8-15: w2 slice) ----
    float wreg[64];
    if (wid < 8) {
        // warp wid owns m = 64r + 8*wid + i, i in 0..7; lane l owns k = l + 32j, j in 0..7
        const float* base = g_w1t + (64u * r + 8u * wid) * NBITS;
        #pragma unroll
        for (int i = 0; i < 8; ++i)
            #pragma unroll
            for (int j = 0; j < 8; ++j)
                wreg[i * 8 + j] = base[i * NBITS + lane + 32 * j];   // coalesced
    } else {
        // warp u=wid-8 owns c = 32r + 4u + i, i in 0..3; lane l owns m = l + 32j, j in 0..15
        const float* base = g_w2t + (32u * r + 4u * (wid - 8)) * MID;
        #pragma unroll
        for (int i = 0; i < 4; ++i)
            #pragma unroll
            for (int j = 0; j < 16; ++j)
                wreg[i * 16 + j] = base[i * MID + lane + 32 * j];    // coalesced
    }
    __syncthreads();
    cluster_bar();                 // all CTAs' smem initialized before DSMEM traffic

    for (int t = Tstar; t < NBITS; ++t) {
        // ---- GEMV1 (warps 0-7): h[64r .. 64r+64) ----
        if (wid < 8) {
            float pv[8];
            #pragma unroll
            for (int j = 0; j < 8; ++j) pv[j] = sm.p_s[lane + 32 * j];   // conflict-free
            float acc[8];
            #pragma unroll
            for (int i = 0; i < 8; ++i) {
                float a = 0.f;
                #pragma unroll
                for (int j = 0; j < 8; ++j) a = fmaf(pv[j], wreg[i * 8 + j], a);
                acc[i] = a;
            }
            #pragma unroll
            for (int i = 0; i < 8; ++i)
                #pragma unroll
                for (int o = 16; o; o >>= 1)
                    acc[i] += __shfl_xor_sync(0xffffffffu, acc[i], o);
            if (lane < 8) {
                float tot = acc[0];
                #pragma unroll
                for (int i = 1; i < 8; ++i) if (lane == i) tot = acc[i];
                int mloc = 8 * wid + lane;
                float hv = gelu_exact(tot + sm.b1_s[mloc]);
                uint32_t la = smem_u32(&sm.h_s[64 * r + mloc]);
                #pragma unroll
                for (uint32_t rk = 0; rk < CLN; ++rk) dsmem_st_f32(la, rk, hv);
            }
        }
        cluster_bar();             // h_s[512] complete everywhere

        // ---- LN (all 16 warps; fixed-order, deterministic) ----
        {
            float hv = sm.h_s[tid];
            float v = hv, v2 = hv * hv;
            #pragma unroll
            for (int o = 16; o; o >>= 1) {
                v  += __shfl_down_sync(0xffffffffu, v,  o);
                v2 += __shfl_down_sync(0xffffffffu, v2, o);
            }
            if (lane == 0) { sm.red_s[wid] = v; sm.red_s[16 + wid] = v2; }
            __syncthreads();
            if (tid == 0) {
                float s = 0.f, q = 0.f;
                #pragma unroll
                for (int i = 0; i < 16; ++i) { s += sm.red_s[i]; q += sm.red_s[16 + i]; }
                float mu  = s * (1.0f / MID);
                float var = q * (1.0f / MID) - mu * mu;
                sm.stat_s[0] = mu;
                sm.stat_s[1] = rsqrtf(var + LN_EPS);
            }
            __syncthreads();
            float mu = sm.stat_s[0], rs = sm.stat_s[1];
            sm.hn_s[tid] = (hv - mu) * rs * sm.gamma_s[tid] + sm.beta_s[tid];
            __syncthreads();
        }

        // ---- GEMV2 (warps 8-15): p cols [32r .. 32r+32) ----
        if (wid >= 8) {
            int u = wid - 8;
            float hnv[16];
            #pragma unroll
            for (int j = 0; j < 16; ++j) hnv[j] = sm.hn_s[lane + 32 * j];  // conflict-free
            float acc[4];
            #pragma unroll
            for (int i = 0; i < 4; ++i) {
                float a = 0.f;
                #pragma unroll
                for (int j = 0; j < 16; ++j) a = fmaf(hnv[j], wreg[i * 16 + j], a);
                acc[i] = a;
            }
            #pragma unroll
            for (int i = 0; i < 4; ++i)
                #pragma unroll
                for (int o = 16; o; o >>= 1)
                    acc[i] += __shfl_xor_sync(0xffffffffu, acc[i], o);
            if (lane < 4) {
                float tot = acc[0];
                #pragma unroll
                for (int i = 1; i < 4; ++i) if (lane == i) tot = acc[i];
                int cl = 4 * u + lane;
                if (sm.winner_s[t * 32 + cl] >= 0) {
                    float pnew = sigmoidf_(tot + sm.b2_s[cl]);
                    uint32_t la = smem_u32(&sm.p_s[32 * r + cl]);
                    #pragma unroll
                    for (uint32_t rk = 0; rk < CLN; ++rk) dsmem_st_f32(la, rk, pnew);
                }
            }
        }
        cluster_bar();             // p_s[256] consistent everywhere
    }

    // ---- output: rows [256r, 256r+256), every row = p_s ----
    {
        const float4* p4 = reinterpret_cast<const float4*>(sm.p_s);
        float4* o4 = reinterpret_cast<float4*>(out);
        for (int i = tid; i < 256 * 64; i += CTHR_C) {
            int srow = 256 * (int)r + (i >> 6);
            o4[srow * 64 + (i & 63)] = p4[i & 63];
        }
    }
}

// ---------------- launch ----------------
extern "C" void kernel_launch(void* const* d_in, const int* in_sizes, int n_in,
                              void* d_out, int out_size) {
    (void)in_sizes; (void)n_in; (void)out_size;
    const float* xs    = (const float*)d_in[0];
    const int*   ids   = (const int*)  d_in[1];
    const float* w1    = (const float*)d_in[2];
    const float* b1    = (const float*)d_in[3];
    const float* gamma = (const float*)d_in[4];
    const float* beta  = (const float*)d_in[5];
    const float* w2    = (const float*)d_in[6];
    const float* b2    = (const float*)d_in[7];
    float* out = (float*)d_out;

    k_tr1<<<dim3(16, 8), dim3(32, 8)>>>(w1);
    k_tr2<<<dim3(8, 16), dim3(32, 8)>>>(w2);
    k_winners<<<8, NTHR>>>(ids);
    k_prep<<<1, NBITS>>>();
    k_full<<<NCTA, NTHR>>>(xs, ids, w1, b1, gamma, beta, b2, out);
    k_collapsed<<<CLN, CTHR_C>>>(b1, gamma, beta, b2, out);
}